// round 2
// baseline (speedup 1.0000x reference)
#include <cuda_runtime.h>
#include <stdint.h>

// Problem constants (fixed shapes per reference_code)
#define NN 100000
#define EE 1600000
#define D  32

// ---------------- scratch (static device globals; no allocation) ----------------
__device__ int   g_deg[NN];
__device__ float g_dinv[NN];
__device__ int   g_rowptr[NN + 1];
__device__ int   g_fill[NN];
__device__ int2  g_cw[EE];        // per (CSR-sorted) edge: {col, float_bits(weight)}
__device__ float g_h [NN * D];    // layer-1 output
__device__ float g_t1[NN * D];    // Tx1
__device__ float g_p [NN * D];    // prop(Tx1)

// ---------------- build kernels ----------------
__global__ void k_zero_deg() {
    int i = blockIdx.x * blockDim.x + threadIdx.x;
    if (i < NN) g_deg[i] = 0;
}

// NOTE: edge_index arrives as int32 (JAX x64 disabled downcasts int64 -> int32).
__global__ void k_hist(const int* __restrict__ ei) {
    int e = blockIdx.x * blockDim.x + threadIdx.x;
    if (e < EE) {
        int r = ei[e];
        int c = ei[EE + e];
        if (r != c) atomicAdd(&g_deg[r], 1);
    }
}

__global__ void k_dinv() {
    int i = blockIdx.x * blockDim.x + threadIdx.x;
    if (i < NN) {
        int d = g_deg[i];
        g_dinv[i] = (d > 0) ? rsqrtf((float)d) : 0.0f;
    }
}

// Single-block exclusive scan of g_deg -> g_rowptr / g_fill (shuffle-based, 1024 thr)
__global__ void k_scan() {
    __shared__ int warp_sums[32];
    __shared__ int s_total;
    const int tid  = threadIdx.x;
    const int lane = tid & 31;
    const int wid  = tid >> 5;
    int run = 0;
    for (int base = 0; base < NN; base += 1024) {
        int i = base + tid;
        int v = (i < NN) ? g_deg[i] : 0;
        // warp-inclusive scan
        int incl = v;
        #pragma unroll
        for (int off = 1; off < 32; off <<= 1) {
            int t = __shfl_up_sync(0xffffffffu, incl, off);
            if (lane >= off) incl += t;
        }
        if (lane == 31) warp_sums[wid] = incl;
        __syncthreads();
        if (wid == 0) {
            int s  = warp_sums[lane];
            int si = s;
            #pragma unroll
            for (int off = 1; off < 32; off <<= 1) {
                int t = __shfl_up_sync(0xffffffffu, si, off);
                if (lane >= off) si += t;
            }
            warp_sums[lane] = si - s;   // exclusive across warps
        }
        __syncthreads();
        int excl = run + warp_sums[wid] + (incl - v);
        if (i < NN) { g_rowptr[i] = excl; g_fill[i] = excl; }
        if (tid == 1023) s_total = excl + v - run;   // chunk total
        __syncthreads();
        run += s_total;
    }
    if (tid == 0) g_rowptr[NN] = run;
}

__global__ void k_scatter(const int* __restrict__ ei) {
    int e = blockIdx.x * blockDim.x + threadIdx.x;
    if (e < EE) {
        int r = ei[e];
        int c = ei[EE + e];
        if (r != c) {
            int pos = atomicAdd(&g_fill[r], 1);
            float w = -g_dinv[r] * g_dinv[c];
            int2 cw;
            cw.x = c;
            cw.y = __float_as_int(w);
            g_cw[pos] = cw;
        }
    }
}

// ---------------- hot path: CSR prop, one warp per row ----------------
__global__ void __launch_bounds__(256) k_prop(const float* __restrict__ src,
                                              float* __restrict__ dst) {
    int warp = (blockIdx.x * blockDim.x + threadIdx.x) >> 5;
    int lane = threadIdx.x & 31;
    if (warp >= NN) return;
    int e    = g_rowptr[warp];
    int eend = g_rowptr[warp + 1];
    float acc = 0.0f;
    for (; e + 4 <= eend; e += 4) {
        int2 a0 = g_cw[e + 0];
        int2 a1 = g_cw[e + 1];
        int2 a2 = g_cw[e + 2];
        int2 a3 = g_cw[e + 3];
        float v0 = src[a0.x * D + lane];
        float v1 = src[a1.x * D + lane];
        float v2 = src[a2.x * D + lane];
        float v3 = src[a3.x * D + lane];
        acc += __int_as_float(a0.y) * v0;
        acc += __int_as_float(a1.y) * v1;
        acc += __int_as_float(a2.y) * v2;
        acc += __int_as_float(a3.y) * v3;
    }
    for (; e < eend; e++) {
        int2 a = g_cw[e];
        acc += __int_as_float(a.y) * src[a.x * D + lane];
    }
    dst[warp * D + lane] = acc;
}

// ---------------- fused epilogue: out = h@(W0-W2) + t1@W1 + 2p@W2 + b (+relu/+resid)
__global__ void __launch_bounds__(128) k_epi(const float* __restrict__ h0,
                                             const float* __restrict__ t1,
                                             const float* __restrict__ pp,
                                             const float* __restrict__ W,
                                             const float* __restrict__ b,
                                             const float* __restrict__ resid,
                                             float* __restrict__ out,
                                             int do_relu) {
    __shared__ float sWc[D * D];
    __shared__ float sW1[D * D];
    __shared__ float sW2[D * D];
    __shared__ float sb[D];
    for (int i = threadIdx.x; i < D * D; i += blockDim.x) {
        sWc[i] = W[i] - W[2 * D * D + i];
        sW1[i] = W[D * D + i];
        sW2[i] = 2.0f * W[2 * D * D + i];
    }
    if (threadIdx.x < D) sb[threadIdx.x] = b[threadIdx.x];
    __syncthreads();

    const int lane = threadIdx.x & 31;
    const int warp = threadIdx.x >> 5;
    const int wpb  = blockDim.x >> 5;
    for (int r = blockIdx.x * wpb + warp; r < NN; r += gridDim.x * wpb) {
        float hv = h0[r * D + lane];
        float tv = t1[r * D + lane];
        float pv = pp[r * D + lane];
        float acc = sb[lane];
        #pragma unroll
        for (int i = 0; i < D; i++) {
            float hi = __shfl_sync(0xffffffffu, hv, i);
            float ti = __shfl_sync(0xffffffffu, tv, i);
            float pi = __shfl_sync(0xffffffffu, pv, i);
            acc += hi * sWc[i * D + lane];
            acc += ti * sW1[i * D + lane];
            acc += pi * sW2[i * D + lane];
        }
        if (do_relu) acc = fmaxf(acc, 0.0f);
        if (resid)   acc += resid[r * D + lane];
        out[r * D + lane] = acc;
    }
}

// ---------------- launch ----------------
extern "C" void kernel_launch(void* const* d_in, const int* in_sizes, int n_in,
                              void* d_out, int out_size) {
    const float* x  = (const float*)d_in[0];
    const int*   ei = (const int*)d_in[1];       // int32 edge_index (2, E)
    const float* W1 = (const float*)d_in[2];
    const float* b1 = (const float*)d_in[3];
    const float* W2 = (const float*)d_in[4];
    const float* b2 = (const float*)d_in[5];
    float*       out = (float*)d_out;

    float *p_h, *p_t1, *p_p;
    cudaGetSymbolAddress((void**)&p_h,  g_h);
    cudaGetSymbolAddress((void**)&p_t1, g_t1);
    cudaGetSymbolAddress((void**)&p_p,  g_p);

    const int TB = 256;
    int gN = (NN + TB - 1) / TB;
    int gE = (EE + TB - 1) / TB;
    int gProp = (NN + 7) / 8;          // 8 warps per 256-thread block
    int gEpi  = 1184;                  // 148 SMs * 8

    // ---- CSR build ----
    k_zero_deg<<<gN, TB>>>();
    k_hist<<<gE, TB>>>(ei);
    k_dinv<<<gN, TB>>>();
    k_scan<<<1, 1024>>>();
    k_scatter<<<gE, TB>>>(ei);

    // ---- layer 1: h = relu(cheb(x; W1,b1)) ----
    k_prop<<<gProp, TB>>>(x,    p_t1);
    k_prop<<<gProp, TB>>>(p_t1, p_p);
    k_epi<<<gEpi, 128>>>(x, p_t1, p_p, W1, b1, (const float*)nullptr, p_h, 1);

    // ---- layer 2 + residual: out = cheb(h; W2,b2) + x ----
    k_prop<<<gProp, TB>>>(p_h,  p_t1);
    k_prop<<<gProp, TB>>>(p_t1, p_p);
    k_epi<<<gEpi, 128>>>(p_h, p_t1, p_p, W2, b2, x, out, 0);
}

// round 3
// speedup vs baseline: 1.1013x; 1.1013x over previous
#include <cuda_runtime.h>
#include <stdint.h>

// Problem constants (fixed shapes per reference_code)
#define NN 100000
#define EE 1600000
#define D  32
#define CHUNK 1024
#define NCH ((NN + CHUNK - 1) / CHUNK)   // 98

// ---------------- scratch (static device globals; no allocation) ----------------
__device__ int   g_deg[NN];
__device__ float g_dinv[NN];
__device__ int   g_rowptr[NN + 1];
__device__ int   g_fill[NN];
__device__ int   g_bsum[NCH];
__device__ int   g_boff[NCH];
__device__ int2  g_cw[EE];        // per (CSR-sorted) edge: {col, float_bits(weight)}
__device__ float g_h [NN * D];    // layer-1 output
__device__ float g_t1[NN * D];    // Tx1
__device__ float g_p [NN * D];    // prop(Tx1)

// ---------------- build kernels ----------------
__global__ void k_zero_deg() {
    int i = blockIdx.x * blockDim.x + threadIdx.x;
    if (i < NN) g_deg[i] = 0;
}

// edge_index arrives as int32 (JAX x64 disabled downcasts int64 -> int32).
__global__ void k_hist(const int* __restrict__ ei) {
    int e = blockIdx.x * blockDim.x + threadIdx.x;
    if (e < EE) {
        int r = ei[e];
        int c = ei[EE + e];
        if (r != c) atomicAdd(&g_deg[r], 1);
    }
}

__global__ void k_dinv() {
    int i = blockIdx.x * blockDim.x + threadIdx.x;
    if (i < NN) {
        int d = g_deg[i];
        g_dinv[i] = (d > 0) ? rsqrtf((float)d) : 0.0f;
    }
}

// ---- parallel 3-phase scan ----
// Phase 1: per-chunk local exclusive scan (1024 threads per block, 1 elem/thread)
__global__ void __launch_bounds__(1024) k_scan1() {
    __shared__ int warp_sums[32];
    const int tid  = threadIdx.x;
    const int lane = tid & 31;
    const int wid  = tid >> 5;
    const int i    = blockIdx.x * CHUNK + tid;
    int v = (i < NN) ? g_deg[i] : 0;
    int incl = v;
    #pragma unroll
    for (int off = 1; off < 32; off <<= 1) {
        int t = __shfl_up_sync(0xffffffffu, incl, off);
        if (lane >= off) incl += t;
    }
    if (lane == 31) warp_sums[wid] = incl;
    __syncthreads();
    if (wid == 0) {
        int s  = warp_sums[lane];
        int si = s;
        #pragma unroll
        for (int off = 1; off < 32; off <<= 1) {
            int t = __shfl_up_sync(0xffffffffu, si, off);
            if (lane >= off) si += t;
        }
        warp_sums[lane] = si - s;   // exclusive across warps
        if (lane == 31) g_bsum[blockIdx.x] = si;   // chunk total
    }
    __syncthreads();
    int excl = warp_sums[wid] + (incl - v);
    if (i < NN) g_rowptr[i] = excl;     // local (chunk-relative) for now
}

// Phase 2: one 128-thread block scans the NCH block sums
__global__ void __launch_bounds__(128) k_scan2() {
    __shared__ int warp_sums[4];
    const int tid  = threadIdx.x;
    const int lane = tid & 31;
    const int wid  = tid >> 5;
    int v = (tid < NCH) ? g_bsum[tid] : 0;
    int incl = v;
    #pragma unroll
    for (int off = 1; off < 32; off <<= 1) {
        int t = __shfl_up_sync(0xffffffffu, incl, off);
        if (lane >= off) incl += t;
    }
    if (lane == 31) warp_sums[wid] = incl;
    __syncthreads();
    int carry = 0;
    #pragma unroll
    for (int w = 0; w < 4; w++) {
        if (w < wid) carry += warp_sums[w];
    }
    int excl = carry + incl - v;
    if (tid < NCH) g_boff[tid] = excl;
    if (tid == NCH - 1) g_rowptr[NN] = excl + v;   // grand total
}

// Phase 3: add block offsets, finalize rowptr & fill
__global__ void __launch_bounds__(1024) k_scan3() {
    int i = blockIdx.x * CHUNK + threadIdx.x;
    if (i < NN) {
        int val = g_rowptr[i] + g_boff[blockIdx.x];
        g_rowptr[i] = val;
        g_fill[i]   = val;
    }
}

__global__ void k_scatter(const int* __restrict__ ei) {
    int e = blockIdx.x * blockDim.x + threadIdx.x;
    if (e < EE) {
        int r = ei[e];
        int c = ei[EE + e];
        if (r != c) {
            int pos = atomicAdd(&g_fill[r], 1);
            float w = -g_dinv[r] * g_dinv[c];
            int2 cw;
            cw.x = c;
            cw.y = __float_as_int(w);
            g_cw[pos] = cw;
        }
    }
}

// ---------------- hot path: CSR prop, one warp per row ----------------
__global__ void __launch_bounds__(256) k_prop(const float* __restrict__ src,
                                              float* __restrict__ dst) {
    int warp = (blockIdx.x * blockDim.x + threadIdx.x) >> 5;
    int lane = threadIdx.x & 31;
    if (warp >= NN) return;
    int e    = g_rowptr[warp];
    int eend = g_rowptr[warp + 1];
    float acc = 0.0f;
    // unroll-8 main loop: 16 independent loads in flight per warp
    for (; e + 8 <= eend; e += 8) {
        int2 a0 = g_cw[e + 0];
        int2 a1 = g_cw[e + 1];
        int2 a2 = g_cw[e + 2];
        int2 a3 = g_cw[e + 3];
        int2 a4 = g_cw[e + 4];
        int2 a5 = g_cw[e + 5];
        int2 a6 = g_cw[e + 6];
        int2 a7 = g_cw[e + 7];
        float v0 = src[a0.x * D + lane];
        float v1 = src[a1.x * D + lane];
        float v2 = src[a2.x * D + lane];
        float v3 = src[a3.x * D + lane];
        float v4 = src[a4.x * D + lane];
        float v5 = src[a5.x * D + lane];
        float v6 = src[a6.x * D + lane];
        float v7 = src[a7.x * D + lane];
        acc += __int_as_float(a0.y) * v0;
        acc += __int_as_float(a1.y) * v1;
        acc += __int_as_float(a2.y) * v2;
        acc += __int_as_float(a3.y) * v3;
        acc += __int_as_float(a4.y) * v4;
        acc += __int_as_float(a5.y) * v5;
        acc += __int_as_float(a6.y) * v6;
        acc += __int_as_float(a7.y) * v7;
    }
    for (; e + 2 <= eend; e += 2) {
        int2 a0 = g_cw[e + 0];
        int2 a1 = g_cw[e + 1];
        float v0 = src[a0.x * D + lane];
        float v1 = src[a1.x * D + lane];
        acc += __int_as_float(a0.y) * v0;
        acc += __int_as_float(a1.y) * v1;
    }
    if (e < eend) {
        int2 a = g_cw[e];
        acc += __int_as_float(a.y) * src[a.x * D + lane];
    }
    dst[warp * D + lane] = acc;
}

// ---------------- fused epilogue: out = h@(W0-W2) + t1@W1 + 2p@W2 + b (+relu/+resid)
__global__ void __launch_bounds__(128) k_epi(const float* __restrict__ h0,
                                             const float* __restrict__ t1,
                                             const float* __restrict__ pp,
                                             const float* __restrict__ W,
                                             const float* __restrict__ b,
                                             const float* __restrict__ resid,
                                             float* __restrict__ out,
                                             int do_relu) {
    __shared__ float sWc[D * D];
    __shared__ float sW1[D * D];
    __shared__ float sW2[D * D];
    __shared__ float sb[D];
    for (int i = threadIdx.x; i < D * D; i += blockDim.x) {
        sWc[i] = W[i] - W[2 * D * D + i];
        sW1[i] = W[D * D + i];
        sW2[i] = 2.0f * W[2 * D * D + i];
    }
    if (threadIdx.x < D) sb[threadIdx.x] = b[threadIdx.x];
    __syncthreads();

    const int lane = threadIdx.x & 31;
    const int warp = threadIdx.x >> 5;
    const int wpb  = blockDim.x >> 5;
    for (int r = blockIdx.x * wpb + warp; r < NN; r += gridDim.x * wpb) {
        float hv = h0[r * D + lane];
        float tv = t1[r * D + lane];
        float pv = pp[r * D + lane];
        float acc = sb[lane];
        #pragma unroll
        for (int i = 0; i < D; i++) {
            float hi = __shfl_sync(0xffffffffu, hv, i);
            float ti = __shfl_sync(0xffffffffu, tv, i);
            float pi = __shfl_sync(0xffffffffu, pv, i);
            acc += hi * sWc[i * D + lane];
            acc += ti * sW1[i * D + lane];
            acc += pi * sW2[i * D + lane];
        }
        if (do_relu) acc = fmaxf(acc, 0.0f);
        if (resid)   acc += resid[r * D + lane];
        out[r * D + lane] = acc;
    }
}

// ---------------- launch ----------------
extern "C" void kernel_launch(void* const* d_in, const int* in_sizes, int n_in,
                              void* d_out, int out_size) {
    const float* x  = (const float*)d_in[0];
    const int*   ei = (const int*)d_in[1];       // int32 edge_index (2, E)
    const float* W1 = (const float*)d_in[2];
    const float* b1 = (const float*)d_in[3];
    const float* W2 = (const float*)d_in[4];
    const float* b2 = (const float*)d_in[5];
    float*       out = (float*)d_out;

    float *p_h, *p_t1, *p_p;
    cudaGetSymbolAddress((void**)&p_h,  g_h);
    cudaGetSymbolAddress((void**)&p_t1, g_t1);
    cudaGetSymbolAddress((void**)&p_p,  g_p);

    const int TB = 256;
    int gN = (NN + TB - 1) / TB;
    int gE = (EE + TB - 1) / TB;
    int gProp = (NN + 7) / 8;          // 8 warps per 256-thread block
    int gEpi  = 1184;                  // 148 SMs * 8

    // ---- CSR build ----
    k_zero_deg<<<gN, TB>>>();
    k_hist<<<gE, TB>>>(ei);
    k_dinv<<<gN, TB>>>();
    k_scan1<<<NCH, 1024>>>();
    k_scan2<<<1, 128>>>();
    k_scan3<<<NCH, 1024>>>();
    k_scatter<<<gE, TB>>>(ei);

    // ---- layer 1: h = relu(cheb(x; W1,b1)) ----
    k_prop<<<gProp, TB>>>(x,    p_t1);
    k_prop<<<gProp, TB>>>(p_t1, p_p);
    k_epi<<<gEpi, 128>>>(x, p_t1, p_p, W1, b1, (const float*)nullptr, p_h, 1);

    // ---- layer 2 + residual: out = cheb(h; W2,b2) + x ----
    k_prop<<<gProp, TB>>>(p_h,  p_t1);
    k_prop<<<gProp, TB>>>(p_t1, p_p);
    k_epi<<<gEpi, 128>>>(p_h, p_t1, p_p, W2, b2, x, out, 0);
}

// round 4
// speedup vs baseline: 1.3996x; 1.2708x over previous
#include <cuda_runtime.h>
#include <stdint.h>

// Problem constants (fixed shapes per reference_code)
#define NN 100000
#define EE 1600000
#define D  32
#define CHUNK 1024
#define NCH ((NN + CHUNK - 1) / CHUNK)   // 98

// ---------------- scratch (static device globals; no allocation) ----------------
__device__ int   g_deg[NN];
__device__ float g_dinv[NN];
__device__ int   g_rowptr[NN + 1];
__device__ int   g_fill[NN];
__device__ int   g_bsum[NCH];
__device__ int   g_boff[NCH];
__device__ int2  g_cw[EE];        // per (CSR-sorted) edge: {col, float_bits(weight)}
__device__ float g_h [NN * D];    // layer-1 output
__device__ float g_t1[NN * D];    // Tx1

// ---------------- build kernels ----------------
__global__ void k_zero_deg() {
    int i = blockIdx.x * blockDim.x + threadIdx.x;
    if (i < NN) g_deg[i] = 0;
}

// edge_index arrives as int32 (JAX x64 disabled downcasts int64 -> int32).
__global__ void k_hist(const int* __restrict__ ei) {
    int e = blockIdx.x * blockDim.x + threadIdx.x;
    if (e < EE) {
        int r = ei[e];
        int c = ei[EE + e];
        if (r != c) atomicAdd(&g_deg[r], 1);
    }
}

__global__ void k_dinv() {
    int i = blockIdx.x * blockDim.x + threadIdx.x;
    if (i < NN) {
        int d = g_deg[i];
        g_dinv[i] = (d > 0) ? rsqrtf((float)d) : 0.0f;
    }
}

// ---- parallel 3-phase scan ----
__global__ void __launch_bounds__(1024) k_scan1() {
    __shared__ int warp_sums[32];
    const int tid  = threadIdx.x;
    const int lane = tid & 31;
    const int wid  = tid >> 5;
    const int i    = blockIdx.x * CHUNK + tid;
    int v = (i < NN) ? g_deg[i] : 0;
    int incl = v;
    #pragma unroll
    for (int off = 1; off < 32; off <<= 1) {
        int t = __shfl_up_sync(0xffffffffu, incl, off);
        if (lane >= off) incl += t;
    }
    if (lane == 31) warp_sums[wid] = incl;
    __syncthreads();
    if (wid == 0) {
        int s  = warp_sums[lane];
        int si = s;
        #pragma unroll
        for (int off = 1; off < 32; off <<= 1) {
            int t = __shfl_up_sync(0xffffffffu, si, off);
            if (lane >= off) si += t;
        }
        warp_sums[lane] = si - s;
        if (lane == 31) g_bsum[blockIdx.x] = si;
    }
    __syncthreads();
    int excl = warp_sums[wid] + (incl - v);
    if (i < NN) g_rowptr[i] = excl;
}

__global__ void __launch_bounds__(128) k_scan2() {
    __shared__ int warp_sums[4];
    const int tid  = threadIdx.x;
    const int lane = tid & 31;
    const int wid  = tid >> 5;
    int v = (tid < NCH) ? g_bsum[tid] : 0;
    int incl = v;
    #pragma unroll
    for (int off = 1; off < 32; off <<= 1) {
        int t = __shfl_up_sync(0xffffffffu, incl, off);
        if (lane >= off) incl += t;
    }
    if (lane == 31) warp_sums[wid] = incl;
    __syncthreads();
    int carry = 0;
    #pragma unroll
    for (int w = 0; w < 4; w++)
        if (w < wid) carry += warp_sums[w];
    int excl = carry + incl - v;
    if (tid < NCH) g_boff[tid] = excl;
    if (tid == NCH - 1) g_rowptr[NN] = excl + v;
}

__global__ void __launch_bounds__(1024) k_scan3() {
    int i = blockIdx.x * CHUNK + threadIdx.x;
    if (i < NN) {
        int val = g_rowptr[i] + g_boff[blockIdx.x];
        g_rowptr[i] = val;
        g_fill[i]   = val;
    }
}

__global__ void k_scatter(const int* __restrict__ ei) {
    int e = blockIdx.x * blockDim.x + threadIdx.x;
    if (e < EE) {
        int r = ei[e];
        int c = ei[EE + e];
        if (r != c) {
            int pos = atomicAdd(&g_fill[r], 1);
            float w = -g_dinv[r] * g_dinv[c];
            int2 cw;
            cw.x = c;
            cw.y = __float_as_int(w);
            g_cw[pos] = cw;
        }
    }
}

// ---------------- gather core: 8 lanes per edge, float4 per lane ----------------
// warp handles one row; sub = lane>>3 picks edge within group-of-4; j = lane&7 picks
// the float4 feature chunk. Result: per-lane partial float4 (sum over sub's edges).
__device__ __forceinline__ float4 gather_row(int e0, int e1, int sub, int j,
                                             const float4* __restrict__ src4) {
    float4 acc = make_float4(0.f, 0.f, 0.f, 0.f);
    int e = e0 + sub;
    for (; e + 4 < e1; e += 8) {
        int2 a0 = g_cw[e];
        int2 a1 = g_cw[e + 4];
        float4 v0 = src4[a0.x * 8 + j];
        float4 v1 = src4[a1.x * 8 + j];
        float w0 = __int_as_float(a0.y);
        float w1 = __int_as_float(a1.y);
        acc.x = fmaf(w0, v0.x, acc.x); acc.y = fmaf(w0, v0.y, acc.y);
        acc.z = fmaf(w0, v0.z, acc.z); acc.w = fmaf(w0, v0.w, acc.w);
        acc.x = fmaf(w1, v1.x, acc.x); acc.y = fmaf(w1, v1.y, acc.y);
        acc.z = fmaf(w1, v1.z, acc.z); acc.w = fmaf(w1, v1.w, acc.w);
    }
    if (e < e1) {
        int2 a = g_cw[e];
        float4 v = src4[a.x * 8 + j];
        float w = __int_as_float(a.y);
        acc.x = fmaf(w, v.x, acc.x); acc.y = fmaf(w, v.y, acc.y);
        acc.z = fmaf(w, v.z, acc.z); acc.w = fmaf(w, v.w, acc.w);
    }
    return acc;
}

__device__ __forceinline__ void reduce_subs(float4& acc) {
    #pragma unroll
    for (int off = 8; off <= 16; off <<= 1) {
        acc.x += __shfl_xor_sync(0xffffffffu, acc.x, off);
        acc.y += __shfl_xor_sync(0xffffffffu, acc.y, off);
        acc.z += __shfl_xor_sync(0xffffffffu, acc.z, off);
        acc.w += __shfl_xor_sync(0xffffffffu, acc.w, off);
    }
}

// ---------------- prop1: dst = L_hat @ src ----------------
__global__ void __launch_bounds__(256) k_prop(const float4* __restrict__ src4,
                                              float4* __restrict__ dst4) {
    int row  = (blockIdx.x * blockDim.x + threadIdx.x) >> 5;
    int lane = threadIdx.x & 31;
    if (row >= NN) return;
    int sub = lane >> 3, j = lane & 7;
    int e0 = g_rowptr[row], e1 = g_rowptr[row + 1];
    float4 acc = gather_row(e0, e1, sub, j, src4);
    reduce_subs(acc);
    if (lane < 8) dst4[row * 8 + lane] = acc;   // lane == j here
}

// ---------------- fused prop2 + epilogue ----------------
// p = L_hat @ t1 (in registers), then out = h0@(W0-W2) + t1@W1 + p@(2*W2) + b
// Weight columns held in registers (96/thread); grid-stride amortizes the load.
__global__ void __launch_bounds__(256, 2) k_prop_epi(
        const float4* __restrict__ t1v,      // t1 as float4 (gather source)
        const float*  __restrict__ t1,       // t1 scalar view (row read)
        const float*  __restrict__ h0,       // Tx0 rows
        const float*  __restrict__ W,        // (3, 32, 32)
        const float*  __restrict__ b,
        const float*  __restrict__ resid,    // nullptr or residual rows
        float*        __restrict__ out,
        int do_relu) {
    const int lane = threadIdx.x & 31;
    const int sub  = lane >> 3, j = lane & 7;
    const int gw   = (blockIdx.x * blockDim.x + threadIdx.x) >> 5;
    const int tot  = (gridDim.x * blockDim.x) >> 5;

    // per-lane weight columns in registers
    float wc[D], w1[D], w2[D];
    #pragma unroll
    for (int i = 0; i < D; i++) {
        float a0 = W[i * D + lane];
        float a1 = W[D * D + i * D + lane];
        float a2 = W[2 * D * D + i * D + lane];
        wc[i] = a0 - a2;
        w1[i] = a1;
        w2[i] = 2.0f * a2;
    }
    const float bias = b[lane];

    for (int row = gw; row < NN; row += tot) {
        int e0 = g_rowptr[row], e1 = g_rowptr[row + 1];
        float4 acc = gather_row(e0, e1, sub, j, t1v);
        reduce_subs(acc);                 // all lanes: full p chunk for j = lane&7
        float hv = h0[row * D + lane];
        float tv = t1[row * D + lane];
        float o = bias;
        #pragma unroll
        for (int i = 0; i < D; i++) {
            float hi = __shfl_sync(0xffffffffu, hv, i);
            float ti = __shfl_sync(0xffffffffu, tv, i);
            float comp = ((i & 3) == 0) ? acc.x :
                         ((i & 3) == 1) ? acc.y :
                         ((i & 3) == 2) ? acc.z : acc.w;
            float pi = __shfl_sync(0xffffffffu, comp, i >> 2);
            o = fmaf(hi, wc[i], o);
            o = fmaf(ti, w1[i], o);
            o = fmaf(pi, w2[i], o);
        }
        if (do_relu) o = fmaxf(o, 0.0f);
        if (resid)   o += resid[row * D + lane];
        out[row * D + lane] = o;
    }
}

// ---------------- launch ----------------
extern "C" void kernel_launch(void* const* d_in, const int* in_sizes, int n_in,
                              void* d_out, int out_size) {
    const float* x  = (const float*)d_in[0];
    const int*   ei = (const int*)d_in[1];       // int32 edge_index (2, E)
    const float* W1 = (const float*)d_in[2];
    const float* b1 = (const float*)d_in[3];
    const float* W2 = (const float*)d_in[4];
    const float* b2 = (const float*)d_in[5];
    float*       out = (float*)d_out;

    float *p_h, *p_t1;
    cudaGetSymbolAddress((void**)&p_h,  g_h);
    cudaGetSymbolAddress((void**)&p_t1, g_t1);

    const int TB = 256;
    int gN = (NN + TB - 1) / TB;
    int gE = (EE + TB - 1) / TB;
    int gProp = (NN + 7) / 8;          // one warp per row
    int gFuse = 296;                   // 148 SMs * 2 resident CTAs

    // ---- CSR build ----
    k_zero_deg<<<gN, TB>>>();
    k_hist<<<gE, TB>>>(ei);
    k_dinv<<<gN, TB>>>();
    k_scan1<<<NCH, 1024>>>();
    k_scan2<<<1, 128>>>();
    k_scan3<<<NCH, 1024>>>();
    k_scatter<<<gE, TB>>>(ei);

    // ---- layer 1: h = relu(cheb(x; W1,b1)) ----
    k_prop<<<gProp, TB>>>((const float4*)x, (float4*)p_t1);
    k_prop_epi<<<gFuse, TB>>>((const float4*)p_t1, p_t1, x, W1, b1,
                              (const float*)nullptr, p_h, 1);

    // ---- layer 2 + residual: out = cheb(h; W2,b2) + x ----
    k_prop<<<gProp, TB>>>((const float4*)p_h, (float4*)p_t1);
    k_prop_epi<<<gFuse, TB>>>((const float4*)p_t1, p_t1, p_h, W2, b2,
                              x, out, 0);
}